// round 2
// baseline (speedup 1.0000x reference)
#include <cuda_runtime.h>
#include <math.h>
#include <stdint.h>

#define NN    8192
#define DD    512
#define NBAGS 64
#define BAG   128
#define TOPK  16

// ---- scratch (static device globals: no allocation at runtime) ----
static __device__ float    g_ninv[NN];              // 1/||f_i||
static __device__ float    g_dis[NN];               // deg^-1/2 per node
static __device__ unsigned g_rowmask[NN][4];        // kept-out-edge bitmask per row (128 bits)
static __device__ float    g_corr[NBAGS * BAG * BAG]; // per-bag cosine blocks (4 MB)
static __device__ float    g_xw[NN * DD];           // features @ W (16 MB)

// ---------------------------------------------------------------------------
// 1) row norms: ninv[i] = 1/sqrt(sum f_i^2)   (norm >> 1e-12 always here)
// ---------------------------------------------------------------------------
__global__ __launch_bounds__(256) void norms_kernel(const float* __restrict__ f) {
    int row  = blockIdx.x * 8 + threadIdx.y;   // blockDim = (32, 8)
    int lane = threadIdx.x;
    const float4* fr = (const float4*)(f + (size_t)row * DD);
    float ss = 0.f;
#pragma unroll
    for (int q = 0; q < 4; q++) {
        float4 v = fr[lane + 32 * q];
        ss += v.x * v.x + v.y * v.y + v.z * v.z + v.w * v.w;
    }
#pragma unroll
    for (int o = 16; o > 0; o >>= 1) ss += __shfl_xor_sync(0xffffffffu, ss, o);
    if (lane == 0) g_ninv[row] = 1.0f / sqrtf(ss);
}

// ---------------------------------------------------------------------------
// 2) per-bag cosine block: corr[g] = nf_bag @ nf_bag^T  (128x128, K=512)
//    grid (2, 64): each block computes a 64x128 half of one bag's block.
// ---------------------------------------------------------------------------
__global__ __launch_bounds__(256) void corr_kernel(const float* __restrict__ features) {
    __shared__ float Fs[32 * 128];   // K-major tile: Fs[k][r]
    __shared__ float ninv_s[128];
    int hy  = blockIdx.x;            // row half: 0 or 1
    int g   = blockIdx.y;            // bag
    int tid = threadIdx.x;
    int tx = tid & 15, ty = tid >> 4;
    int rbase = hy * 64;
    const float* fb = features + (size_t)g * BAG * DD;
    if (tid < 128) ninv_s[tid] = g_ninv[g * BAG + tid];

    float acc[4][8];
#pragma unroll
    for (int i = 0; i < 4; i++)
#pragma unroll
        for (int j = 0; j < 8; j++) acc[i][j] = 0.f;

    for (int k0 = 0; k0 < DD; k0 += 32) {
        __syncthreads();
#pragma unroll
        for (int p = 0; p < 4; p++) {          // load 128x32 tile, transposed into Fs
            int r = (tid >> 3) + p * 32;
            int k = (tid & 7) << 2;
            float4 v = *(const float4*)(fb + (size_t)r * DD + k0 + k);
            Fs[(k + 0) * 128 + r] = v.x;
            Fs[(k + 1) * 128 + r] = v.y;
            Fs[(k + 2) * 128 + r] = v.z;
            Fs[(k + 3) * 128 + r] = v.w;
        }
        __syncthreads();
#pragma unroll 8
        for (int k = 0; k < 32; k++) {
            float4 av = *(const float4*)&Fs[k * 128 + rbase + ty * 4];
            float4 b0 = *(const float4*)&Fs[k * 128 + tx * 8];
            float4 b1 = *(const float4*)&Fs[k * 128 + tx * 8 + 4];
            float a[4] = {av.x, av.y, av.z, av.w};
            float b[8] = {b0.x, b0.y, b0.z, b0.w, b1.x, b1.y, b1.z, b1.w};
#pragma unroll
            for (int i = 0; i < 4; i++)
#pragma unroll
                for (int j = 0; j < 8; j++) acc[i][j] = fmaf(a[i], b[j], acc[i][j]);
        }
    }

    float* cg = g_corr + (size_t)g * BAG * BAG;
    float nj[8];
#pragma unroll
    for (int j = 0; j < 8; j++) nj[j] = ninv_s[tx * 8 + j];
#pragma unroll
    for (int i = 0; i < 4; i++) {
        int row = rbase + ty * 4 + i;
        float ni = ninv_s[row];
#pragma unroll
        for (int j0 = 0; j0 < 8; j0 += 4) {
            float4 v;
            v.x = acc[i][j0 + 0] * ni * nj[j0 + 0];
            v.y = acc[i][j0 + 1] * ni * nj[j0 + 1];
            v.z = acc[i][j0 + 2] * ni * nj[j0 + 2];
            v.w = acc[i][j0 + 3] * ni * nj[j0 + 3];
            *(float4*)&cg[(size_t)row * BAG + tx * 8 + j0] = v;
        }
    }
}

// ---------------------------------------------------------------------------
// 3) per-row top-16 (values > 0 survive; negatives are displaced by the 8064
//    exact zeros outside the bag). One warp per row, 16 iterative arg-maxes
//    with lowest-index tie-break (jax top_k order). Writes kept adj values,
//    row bitmasks, and column in-degrees -> dis = deg^-1/2.
// ---------------------------------------------------------------------------
__global__ __launch_bounds__(256) void topk_kernel(float* __restrict__ adj) {
    __shared__ int deg_s[128];
    int g = blockIdx.x, tid = threadIdx.x;
    int warp = tid >> 5, lane = tid & 31;
    if (tid < 128) deg_s[tid] = 0;
    __syncthreads();

    for (int rr = 0; rr < 16; rr++) {
        int i = warp * 16 + rr;
        const float* row = g_corr + ((size_t)g * BAG + i) * BAG;
        float v0 = row[lane], v1 = row[lane + 32], v2 = row[lane + 64], v3 = row[lane + 96];
        unsigned rm0 = 0, rm1 = 0, rm2 = 0, rm3 = 0;

        for (int t = 0; t < TOPK; t++) {
            float bv = v0; int bidx = lane;
            if (v1 > bv) { bv = v1; bidx = lane + 32; }
            if (v2 > bv) { bv = v2; bidx = lane + 64; }
            if (v3 > bv) { bv = v3; bidx = lane + 96; }
#pragma unroll
            for (int o = 16; o > 0; o >>= 1) {
                float ov = __shfl_xor_sync(0xffffffffu, bv, o);
                int   oi = __shfl_xor_sync(0xffffffffu, bidx, o);
                if (ov > bv || (ov == bv && oi < bidx)) { bv = ov; bidx = oi; }
            }
            if (bv <= 0.0f) break;  // all remaining in-bag values lose to zeros
            if ((bidx & 31) == lane) {   // clear the winner
                int q = bidx >> 5;
                if (q == 0) v0 = -3e38f; else if (q == 1) v1 = -3e38f;
                else if (q == 2) v2 = -3e38f; else v3 = -3e38f;
            }
            int q = bidx >> 5; unsigned bit = 1u << (bidx & 31);
            rm0 |= (q == 0) ? bit : 0u; rm1 |= (q == 1) ? bit : 0u;
            rm2 |= (q == 2) ? bit : 0u; rm3 |= (q == 3) ? bit : 0u;
            if (lane == 0) {
                adj[((size_t)(g * BAG + i)) * NN + g * BAG + bidx] = bv;
                atomicAdd(&deg_s[bidx], 1);
            }
        }
        if (lane == 0) {
            g_rowmask[g * BAG + i][0] = rm0;
            g_rowmask[g * BAG + i][1] = rm1;
            g_rowmask[g * BAG + i][2] = rm2;
            g_rowmask[g * BAG + i][3] = rm3;
        }
    }
    __syncthreads();
    if (tid < 128) g_dis[g * BAG + tid] = 1.0f / sqrtf((float)deg_s[tid]);
}

// ---------------------------------------------------------------------------
// 4) xw = features @ W   (8192x512 @ 512x512, fp32 tiled SIMT GEMM)
// ---------------------------------------------------------------------------
__global__ __launch_bounds__(256) void xw_kernel(const float* __restrict__ A,
                                                 const float* __restrict__ B) {
    __shared__ float As[16 * 128];   // As[k][m]
    __shared__ float Bs[16 * 128];   // Bs[k][n]
    int tid = threadIdx.x;
    int tx = tid & 15, ty = tid >> 4;
    int n0 = blockIdx.x * 128;
    int m0 = blockIdx.y * 128;

    float acc[8][8];
#pragma unroll
    for (int i = 0; i < 8; i++)
#pragma unroll
        for (int j = 0; j < 8; j++) acc[i][j] = 0.f;

    for (int k0 = 0; k0 < DD; k0 += 16) {
        __syncthreads();
#pragma unroll
        for (int p = 0; p < 2; p++) {   // A tile 128x16 -> transposed
            int r = (tid >> 2) + p * 64;
            int k = (tid & 3) << 2;
            float4 v = *(const float4*)(A + (size_t)(m0 + r) * DD + k0 + k);
            As[(k + 0) * 128 + r] = v.x;
            As[(k + 1) * 128 + r] = v.y;
            As[(k + 2) * 128 + r] = v.z;
            As[(k + 3) * 128 + r] = v.w;
        }
#pragma unroll
        for (int p = 0; p < 2; p++) {   // B tile 16x128, natural layout
            int k = (tid >> 5) + p * 8;
            int n = (tid & 31) << 2;
            *(float4*)&Bs[k * 128 + n] = *(const float4*)(B + (size_t)(k0 + k) * DD + n0 + n);
        }
        __syncthreads();
#pragma unroll 8
        for (int k = 0; k < 16; k++) {
            float4 a0 = *(const float4*)&As[k * 128 + ty * 8];
            float4 a1 = *(const float4*)&As[k * 128 + ty * 8 + 4];
            float4 b0 = *(const float4*)&Bs[k * 128 + tx * 8];
            float4 b1 = *(const float4*)&Bs[k * 128 + tx * 8 + 4];
            float a[8] = {a0.x, a0.y, a0.z, a0.w, a1.x, a1.y, a1.z, a1.w};
            float b[8] = {b0.x, b0.y, b0.z, b0.w, b1.x, b1.y, b1.z, b1.w};
#pragma unroll
            for (int i = 0; i < 8; i++)
#pragma unroll
                for (int j = 0; j < 8; j++) acc[i][j] = fmaf(a[i], b[j], acc[i][j]);
        }
    }
#pragma unroll
    for (int i = 0; i < 8; i++) {
        int m = m0 + ty * 8 + i;
#pragma unroll
        for (int j0 = 0; j0 < 8; j0 += 4) {
            float4 v = make_float4(acc[i][j0], acc[i][j0 + 1], acc[i][j0 + 2], acc[i][j0 + 3]);
            *(float4*)&g_xw[(size_t)m * DD + n0 + tx * 8 + j0] = v;
        }
    }
}

// ---------------------------------------------------------------------------
// 5) agg[g,d] = sum_i w_i * xw[g*128+i, d] + 128*b[d]
//    with w_i = dis[i] * sum_{j in rowmask(i)} dis[j]
//    (valid because all edges are in-bag and agg sums the whole bag)
// ---------------------------------------------------------------------------
__global__ __launch_bounds__(256) void gcn_kernel(const float* __restrict__ b,
                                                  float* __restrict__ agg) {
    __shared__ float    dis_s[128];
    __shared__ float    w_s[128];
    __shared__ unsigned rm_s[128][4];
    int g = blockIdx.x, tid = threadIdx.x;
    if (tid < 128) {
        dis_s[tid] = g_dis[g * BAG + tid];
#pragma unroll
        for (int q = 0; q < 4; q++) rm_s[tid][q] = g_rowmask[g * BAG + tid][q];
    }
    __syncthreads();
    if (tid < 128) {
        float s = 0.f;
#pragma unroll
        for (int q = 0; q < 4; q++) {
            unsigned m = rm_s[tid][q];
            while (m) { int j = __ffs(m) - 1; s += dis_s[q * 32 + j]; m &= m - 1; }
        }
        w_s[tid] = dis_s[tid] * s;
    }
    __syncthreads();
    const float* xwb = g_xw + (size_t)g * BAG * DD;
    float a0 = 128.0f * b[tid];
    float a1 = 128.0f * b[tid + 256];
    for (int i = 0; i < BAG; i++) {
        float wi = w_s[i];
        a0 = fmaf(wi, xwb[i * DD + tid], a0);
        a1 = fmaf(wi, xwb[i * DD + tid + 256], a1);
    }
    agg[g * DD + tid] = a0;
    agg[g * DD + tid + 256] = a1;
}

// ---------------------------------------------------------------------------
extern "C" void kernel_launch(void* const* d_in, const int* in_sizes, int n_in,
                              void* d_out, int out_size) {
    (void)in_sizes; (void)n_in;
    const float* features = (const float*)d_in[0];
    const float* W        = (const float*)d_in[1];
    const float* b        = (const float*)d_in[2];

    float* out = (float*)d_out;
    // outputs concatenated in reference-return order: agg [64,512], adj [8192,8192]
    float* agg = out;
    float* adj = out + ((size_t)out_size - (size_t)NN * NN);

    // zero everything (adj is ~0.2% dense; agg fully overwritten later)
    cudaMemsetAsync(d_out, 0, (size_t)out_size * sizeof(float), 0);

    norms_kernel<<<NN / 8, dim3(32, 8)>>>(features);
    corr_kernel<<<dim3(2, NBAGS), 256>>>(features);
    topk_kernel<<<NBAGS, 256>>>(adj);
    xw_kernel<<<dim3(DD / 128, NN / 128), 256>>>(features, W);
    gcn_kernel<<<NBAGS, 256>>>(b, agg);
}

// round 5
// speedup vs baseline: 1.3310x; 1.3310x over previous
#include <cuda_runtime.h>
#include <math.h>
#include <stdint.h>

#define NN    8192
#define DD    512
#define NBAGS 64
#define BAG   128
#define TOPK  16

#define XW_BLOCKS   256
#define CORR_BLOCKS 64
#define A_BLOCKS    (XW_BLOCKS + CORR_BLOCKS)

// ---- scratch (static device globals: no allocation at runtime) ----
static __device__ float g_corr[NBAGS * BAG * BAG]; // per-bag cosine blocks (4 MB)
static __device__ float g_xw[NN * DD];             // features @ W (16 MB)

// ---------------------------------------------------------------------------
// Kernel A: one launch, three concurrent roles.
//   every block : zero a grid-strided slice of the 268 MB output
//   bid <  256  : xw = features @ W tile (128x128, double-buffered smem)
//   bid >= 256  : corr[bag] = nf@nf^T (128x128, K=512), ninv from own diagonal
// ---------------------------------------------------------------------------
__global__ __launch_bounds__(256, 2) void fused_A(const float* __restrict__ A,
                                                  const float* __restrict__ W,
                                                  float4* __restrict__ outz,
                                                  int total4) {
    __shared__ float sh[2 * 16 * 132 + 2 * 16 * 128]; // 8448 floats (33 KB)
    __shared__ float ninv_s[128];
    int tid = threadIdx.x;
    int bid = blockIdx.x;

    // ---- zero-fill slice of d_out (fire-and-forget stores) ----
    {
        float4 z = make_float4(0.f, 0.f, 0.f, 0.f);
        for (size_t i = (size_t)bid * 256 + tid; i < (size_t)total4;
             i += (size_t)A_BLOCKS * 256)
            outz[i] = z;
    }

    int tx = tid & 15, ty = tid >> 4;
    int ar = tid >> 2;            // 0..63
    int ak = (tid & 3) << 2;      // 0,4,8,12

    float acc[8][8];
#pragma unroll
    for (int i = 0; i < 8; i++)
#pragma unroll
        for (int j = 0; j < 8; j++) acc[i][j] = 0.f;

    if (bid < XW_BLOCKS) {
        // ================= xw GEMM tile =================
        float* As = sh;            // 2 x (16*132)
        float* Bs = sh + 2 * 2112; // 2 x (16*128)
        int n0 = (bid & 3) * 128;
        int m0 = (bid >> 2) * 128;
        int bkr = tid >> 5;            // 0..7
        int bn  = (tid & 31) << 2;     // 0..124

        const float* Ap0 = A + (size_t)(m0 + ar) * DD + ak;
        const float* Ap1 = Ap0 + (size_t)64 * DD;
        const float* Bp0 = W + (size_t)bkr * DD + n0 + bn;
        const float* Bp1 = Bp0 + (size_t)8 * DD;

        float4 ra0 = *(const float4*)(Ap0);
        float4 ra1 = *(const float4*)(Ap1);
        float4 rb0 = *(const float4*)(Bp0);
        float4 rb1 = *(const float4*)(Bp1);

        int buf = 0;
        for (int k0 = 0; k0 < DD; k0 += 16) {
            float* as = As + buf * 2112;
            float* bs = Bs + buf * 2048;
            as[(ak + 0) * 132 + ar] = ra0.x;
            as[(ak + 1) * 132 + ar] = ra0.y;
            as[(ak + 2) * 132 + ar] = ra0.z;
            as[(ak + 3) * 132 + ar] = ra0.w;
            as[(ak + 0) * 132 + ar + 64] = ra1.x;
            as[(ak + 1) * 132 + ar + 64] = ra1.y;
            as[(ak + 2) * 132 + ar + 64] = ra1.z;
            as[(ak + 3) * 132 + ar + 64] = ra1.w;
            *(float4*)&bs[bkr * 128 + bn] = rb0;
            *(float4*)&bs[(bkr + 8) * 128 + bn] = rb1;
            __syncthreads();

            if (k0 + 16 < DD) {
                ra0 = *(const float4*)(Ap0 + k0 + 16);
                ra1 = *(const float4*)(Ap1 + k0 + 16);
                rb0 = *(const float4*)(Bp0 + (size_t)(k0 + 16) * DD);
                rb1 = *(const float4*)(Bp1 + (size_t)(k0 + 16) * DD);
            }

#pragma unroll
            for (int k = 0; k < 16; k++) {
                float4 a0 = *(const float4*)&as[k * 132 + ty * 8];
                float4 a1 = *(const float4*)&as[k * 132 + ty * 8 + 4];
                float4 b0 = *(const float4*)&bs[k * 128 + tx * 8];
                float4 b1 = *(const float4*)&bs[k * 128 + tx * 8 + 4];
                float a[8] = {a0.x, a0.y, a0.z, a0.w, a1.x, a1.y, a1.z, a1.w};
                float b[8] = {b0.x, b0.y, b0.z, b0.w, b1.x, b1.y, b1.z, b1.w};
#pragma unroll
                for (int i = 0; i < 8; i++)
#pragma unroll
                    for (int j = 0; j < 8; j++) acc[i][j] = fmaf(a[i], b[j], acc[i][j]);
            }
            buf ^= 1;
        }

#pragma unroll
        for (int i = 0; i < 8; i++) {
            int m = m0 + ty * 8 + i;
#pragma unroll
            for (int j0 = 0; j0 < 8; j0 += 4) {
                float4 v = make_float4(acc[i][j0], acc[i][j0 + 1],
                                       acc[i][j0 + 2], acc[i][j0 + 3]);
                *(float4*)&g_xw[(size_t)m * DD + n0 + tx * 8 + j0] = v;
            }
        }
    } else {
        // ================= corr bag block =================
        int g = bid - XW_BLOCKS;
        float* Cs = sh;  // 2 x (16*132)
        const float* fb = A + (size_t)g * BAG * DD;
        const float* Cp0 = fb + (size_t)ar * DD + ak;
        const float* Cp1 = Cp0 + (size_t)64 * DD;

        float4 rc0 = *(const float4*)(Cp0);
        float4 rc1 = *(const float4*)(Cp1);

        int buf = 0;
        for (int k0 = 0; k0 < DD; k0 += 16) {
            float* cs = Cs + buf * 2112;
            cs[(ak + 0) * 132 + ar] = rc0.x;
            cs[(ak + 1) * 132 + ar] = rc0.y;
            cs[(ak + 2) * 132 + ar] = rc0.z;
            cs[(ak + 3) * 132 + ar] = rc0.w;
            cs[(ak + 0) * 132 + ar + 64] = rc1.x;
            cs[(ak + 1) * 132 + ar + 64] = rc1.y;
            cs[(ak + 2) * 132 + ar + 64] = rc1.z;
            cs[(ak + 3) * 132 + ar + 64] = rc1.w;
            __syncthreads();

            if (k0 + 16 < DD) {
                rc0 = *(const float4*)(Cp0 + k0 + 16);
                rc1 = *(const float4*)(Cp1 + k0 + 16);
            }

#pragma unroll
            for (int k = 0; k < 16; k++) {
                float4 a0 = *(const float4*)&cs[k * 132 + ty * 8];
                float4 a1 = *(const float4*)&cs[k * 132 + ty * 8 + 4];
                float4 b0 = *(const float4*)&cs[k * 132 + tx * 8];
                float4 b1 = *(const float4*)&cs[k * 132 + tx * 8 + 4];
                float a[8] = {a0.x, a0.y, a0.z, a0.w, a1.x, a1.y, a1.z, a1.w};
                float b[8] = {b0.x, b0.y, b0.z, b0.w, b1.x, b1.y, b1.z, b1.w};
#pragma unroll
                for (int i = 0; i < 8; i++)
#pragma unroll
                    for (int j = 0; j < 8; j++) acc[i][j] = fmaf(a[i], b[j], acc[i][j]);
            }
            buf ^= 1;
        }

        // diagonal -> row norms (corr[i][i] = ||f_i||^2)
        if (tx == ty) {
#pragma unroll
            for (int ii = 0; ii < 8; ii++) ninv_s[ty * 8 + ii] = acc[ii][ii];
        }
        __syncthreads();
        if (tid < 128) ninv_s[tid] = 1.0f / sqrtf(ninv_s[tid]);
        __syncthreads();

        float* cg = g_corr + (size_t)g * BAG * BAG;
        float nj[8];
#pragma unroll
        for (int j = 0; j < 8; j++) nj[j] = ninv_s[tx * 8 + j];
#pragma unroll
        for (int i = 0; i < 8; i++) {
            int row = ty * 8 + i;
            float ni = ninv_s[row];
#pragma unroll
            for (int j0 = 0; j0 < 8; j0 += 4) {
                float4 v;
                v.x = acc[i][j0 + 0] * ni * nj[j0 + 0];
                v.y = acc[i][j0 + 1] * ni * nj[j0 + 1];
                v.z = acc[i][j0 + 2] * ni * nj[j0 + 2];
                v.w = acc[i][j0 + 3] * ni * nj[j0 + 3];
                *(float4*)&cg[(size_t)row * BAG + tx * 8 + j0] = v;
            }
        }
    }
}

// ---------------------------------------------------------------------------
// Kernel B: per-bag top-16 + GCN aggregate, fully fused (1024 threads/bag).
//   phase 1: 32 warps x 4 rows, iterative warp argmax (lowest-index tie-break),
//            writes kept adj values, smem degrees + row bitmasks
//   phase 2: w_i = dis_i * sum_{j in rowmask(i)} dis_j
//   phase 3: agg[g,d] = sum_i w_i * xw[g*128+i, d] + 128*b[d]
// ---------------------------------------------------------------------------
__global__ __launch_bounds__(1024) void fused_B(const float* __restrict__ b,
                                                float* __restrict__ agg,
                                                float* __restrict__ adj) {
    __shared__ int      deg_s[128];
    __shared__ unsigned rm_s[128][4];
    __shared__ float    dis_s[128];
    __shared__ float    w_s[128];
    __shared__ float    part[512];
    int g = blockIdx.x, tid = threadIdx.x;
    int warp = tid >> 5, lane = tid & 31;
    if (tid < 128) deg_s[tid] = 0;
    __syncthreads();

    for (int rr = 0; rr < 4; rr++) {
        int i = warp * 4 + rr;
        const float* row = g_corr + ((size_t)g * BAG + i) * BAG;
        float v0 = row[lane], v1 = row[lane + 32], v2 = row[lane + 64], v3 = row[lane + 96];
        unsigned rm0 = 0, rm1 = 0, rm2 = 0, rm3 = 0;

        for (int t = 0; t < TOPK; t++) {
            float bv = v0; int bidx = lane;
            if (v1 > bv) { bv = v1; bidx = lane + 32; }
            if (v2 > bv) { bv = v2; bidx = lane + 64; }
            if (v3 > bv) { bv = v3; bidx = lane + 96; }
#pragma unroll
            for (int o = 16; o > 0; o >>= 1) {
                float ov = __shfl_xor_sync(0xffffffffu, bv, o);
                int   oi = __shfl_xor_sync(0xffffffffu, bidx, o);
                if (ov > bv || (ov == bv && oi < bidx)) { bv = ov; bidx = oi; }
            }
            if (bv <= 0.0f) break;  // remaining in-bag values lose to out-of-bag zeros
            if ((bidx & 31) == lane) {   // clear the winner
                int q = bidx >> 5;
                if (q == 0) v0 = -3e38f; else if (q == 1) v1 = -3e38f;
                else if (q == 2) v2 = -3e38f; else v3 = -3e38f;
            }
            int q = bidx >> 5; unsigned bit = 1u << (bidx & 31);
            rm0 |= (q == 0) ? bit : 0u; rm1 |= (q == 1) ? bit : 0u;
            rm2 |= (q == 2) ? bit : 0u; rm3 |= (q == 3) ? bit : 0u;
            if (lane == 0) {
                adj[((size_t)(g * BAG + i)) * NN + g * BAG + bidx] = bv;
                atomicAdd(&deg_s[bidx], 1);
            }
        }
        if (lane == 0) {
            rm_s[i][0] = rm0; rm_s[i][1] = rm1; rm_s[i][2] = rm2; rm_s[i][3] = rm3;
        }
    }
    __syncthreads();
    if (tid < 128) dis_s[tid] = 1.0f / sqrtf((float)deg_s[tid]);
    __syncthreads();
    if (tid < 128) {
        float s = 0.f;
#pragma unroll
        for (int q = 0; q < 4; q++) {
            unsigned m = rm_s[tid][q];
            while (m) { int j = __ffs(m) - 1; s += dis_s[q * 32 + j]; m &= m - 1; }
        }
        w_s[tid] = dis_s[tid] * s;
    }
    __syncthreads();

    // phase 3: 1024 threads = 512 cols x 2 row-halves
    int col = tid & 511, half = tid >> 9;
    const float* xwb = g_xw + (size_t)g * BAG * DD + (size_t)half * 64 * DD + col;
    float a = 0.f;
#pragma unroll 8
    for (int i = 0; i < 64; i++)
        a = fmaf(w_s[half * 64 + i], xwb[(size_t)i * DD], a);
    if (half) part[col] = a;
    __syncthreads();
    if (!half) agg[g * DD + col] = a + part[col] + 128.0f * b[col];
}

// ---------------------------------------------------------------------------
// Two launches, single stream, no streams/events (nothing to leak):
//   A (zero-out + xw + corr concurrently) -> B (topk + gcn)
// ---------------------------------------------------------------------------
extern "C" void kernel_launch(void* const* d_in, const int* in_sizes, int n_in,
                              void* d_out, int out_size) {
    (void)in_sizes; (void)n_in;
    const float* features = (const float*)d_in[0];
    const float* W        = (const float*)d_in[1];
    const float* b        = (const float*)d_in[2];

    float* out = (float*)d_out;
    float* agg = out;                                        // [64, 512]
    float* adj = out + ((size_t)out_size - (size_t)NN * NN); // [8192, 8192]

    fused_A<<<A_BLOCKS, 256>>>(features, W, (float4*)d_out, out_size / 4);
    fused_B<<<NBAGS, 1024>>>(b, agg, adj);
}